// round 17
// baseline (speedup 1.0000x reference)
#include <cuda_runtime.h>
#include <cuda_bf16.h>
#include <cstdint>

// Yolov1 loss — warp-specialized persistent kernel: 1 producer warp feeds a
// 12-stage cp.async ring; 7 consumer warps compute.
// FIX vs R16: cp.async.mbarrier.arrive must be the .noinc form — the default
// form increments the pending count before arriving (net zero) and deadlocks.
// B=16384, cells = 802816 = 25088 tiles of 32 cells (3840 B per tile).
// 444 blocks; block b owns tiles [b*56+min(b,224), +cnt), cnt = 56+(b<224).
// Consumer warp w computes tiles j == w (mod 7); stage = j % 12.
// Cell layout: [0:2) conf, [2:10) boxes (NB,4), [10:30) class logits.

#define NBLOCKS  444
#define NTHREADS 256
#define NTILES   25088
#define NEXTRA   (NTILES - NBLOCKS * 56)   // 224
#define NSTAGES  12
#define TWORDS   960

__device__ float g_partials[NBLOCKS];
__device__ unsigned int g_done = 0;   // atomicInc mod NBLOCKS -> self-resetting

__device__ __forceinline__ float fsig(float x) {
    float t;
    asm("tanh.approx.f32 %0, %1;" : "=f"(t) : "f"(x * 0.5f));
    return fmaf(t, 0.5f, 0.5f);
}
__device__ __forceinline__ float fsqrt_a(float x) {
    float r;
    asm("sqrt.approx.f32 %0, %1;" : "=f"(r) : "f"(x));
    return r;
}
__device__ __forceinline__ unsigned int smem_u32(const void* p) {
    return (unsigned int)__cvta_generic_to_shared(p);
}
__device__ __forceinline__ void mbar_init(unsigned int bar, unsigned int cnt) {
    asm volatile("mbarrier.init.shared.b64 [%0], %1;" :: "r"(bar), "r"(cnt) : "memory");
}
__device__ __forceinline__ void mbar_arrive(unsigned int bar) {
    asm volatile("mbarrier.arrive.shared.b64 _, [%0];" :: "r"(bar) : "memory");
}
// Arrive (without count increment) when this thread's prior cp.asyncs complete.
__device__ __forceinline__ void cpasync_mbar_arrive_noinc(unsigned int bar) {
    asm volatile("cp.async.mbarrier.arrive.noinc.shared.b64 [%0];" :: "r"(bar) : "memory");
}
__device__ __forceinline__ void mbar_wait(unsigned int bar, unsigned int parity) {
    unsigned int done;
    asm volatile(
        "{\n\t"
        ".reg .pred p;\n\t"
        "mbarrier.try_wait.parity.acquire.cta.shared::cta.b64 p, [%1], %2;\n\t"
        "selp.b32 %0, 1, 0, p;\n\t"
        "}"
        : "=r"(done) : "r"(bar), "r"(parity) : "memory");
    if (!done) {
        asm volatile(
            "{\n\t"
            ".reg .pred P1;\n\t"
            "WAIT_LOOP_%=:\n\t"
            "mbarrier.try_wait.parity.acquire.cta.shared::cta.b64 P1, [%0], %1, 0x989680;\n\t"
            "@P1 bra.uni WAIT_DONE_%=;\n\t"
            "bra.uni WAIT_LOOP_%=;\n\t"
            "WAIT_DONE_%=:\n\t"
            "}"
            :: "r"(bar), "r"(parity) : "memory");
    }
}

// One cell's loss. p = 30 floats in smem; target data already in registers.
__device__ __forceinline__ float cell_loss(const float* __restrict__ p, int t,
                                           float4 tb, int g, int tc)
{
    const int s = t % 49;
    const float xg = (float)(s % 7);
    const float yg = (float)(s / 7);
    const float inv7 = 1.0f / 7.0f;
    const float tox = tb.x, toy = tb.y, tw = tb.z, th = tb.w;

    const float conf0 = fsig(p[0]);
    const float conf1 = fsig(p[1]);
    float pb[2][4];
    #pragma unroll
    for (int nb = 0; nb < 2; nb++)
        #pragma unroll
        for (int k = 0; k < 4; k++)
            pb[nb][k] = fsig(p[2 + nb * 4 + k]);

    float esum = 0.0f, et = 0.0f;
    #pragma unroll
    for (int j = 0; j < 20; j++) {
        const float e = __expf(p[10 + j]);
        esum += e;
        if (j == tc) et = e;
    }
    const float cls_t = __fdividef(et, esum);

    const float tcx = (xg + tox) * inv7;
    const float tcy = (yg + toy) * inv7;
    float iou[2];
    #pragma unroll
    for (int nb = 0; nb < 2; nb++) {
        const float pcx = (xg + pb[nb][0]) * inv7;
        const float pcy = (yg + pb[nb][1]) * inv7;
        const float pw = pb[nb][2], ph = pb[nb][3];
        const float tb_ = fminf(tcx + tw * 0.5f, pcx + pw * 0.5f)
                        - fmaxf(tcx - tw * 0.5f, pcx - pw * 0.5f);
        const float lr_ = fminf(tcy + th * 0.5f, pcy + ph * 0.5f)
                        - fmaxf(tcy - th * 0.5f, pcy - ph * 0.5f);
        const float inter = (tb_ < 0.0f || lr_ < 0.0f) ? 0.0f : tb_ * lr_;
        iou[nb] = __fdividef(inter, tw * th + pw * ph - inter);
    }

    const int best = (iou[1] > iou[0]) ? 1 : 0;
    const float iou_b  = iou[best];
    const float conf_b = best ? conf1 : conf0;

    const float d0 = pb[best][0] - tox;
    const float d1 = pb[best][1] - toy;
    const float d2 = fsqrt_a(pb[best][2]) - fsqrt_a(tw);
    const float d3 = fsqrt_a(pb[best][3]) - fsqrt_a(th);
    const float coord = d0 * d0 + d1 * d1 + d2 * d2 + d3 * d3;

    const float dc = conf_b - iou_b;
    const float dl = 1.0f - cls_t;
    const float obj_loss   = 5.0f * coord + dc * dc + dl * dl;
    const float noobj_loss = 0.5f * (conf0 * conf0 + conf1 * conf1);
    return (g == 1) ? obj_loss : noobj_loss;
}

// Issue one tile's cp.async copies (240 float4 over the warp), no barrier ops.
__device__ __forceinline__ void issue_tile(float* __restrict__ dst,
                                           const float4* __restrict__ pred4,
                                           int tile, int lane)
{
    const float4* src = pred4 + (long)tile * 240;
    #pragma unroll
    for (int i = 0; i < 8; i++) {
        const int idx = lane + i * 32;
        if (idx < 240) {
            const unsigned int da = smem_u32(dst + idx * 4);
            asm volatile("cp.async.cg.shared.global [%0], [%1], 16;"
                         :: "r"(da), "l"(src + idx));
        }
    }
}

__global__ __launch_bounds__(NTHREADS, 3)
void yolo_loss_kernel(const float* __restrict__ pred,
                      const int*   __restrict__ grid,
                      const float* __restrict__ tbox,
                      const int*   __restrict__ tcls,
                      float* __restrict__ out)
{
    // 12 stages * 960 floats = 46080 B ring (+ barriers)
    __shared__ __align__(16) float sp[NSTAGES * TWORDS];
    __shared__ __align__(8) unsigned long long full_b[NSTAGES], empty_b[NSTAGES];
    __shared__ float wsum[NTHREADS / 32];
    __shared__ bool s_last;

    const int lane = threadIdx.x & 31;
    const int wid  = threadIdx.x >> 5;

    const int start = blockIdx.x * 56 + min((int)blockIdx.x, NEXTRA);
    const int cnt   = 56 + (blockIdx.x < NEXTRA ? 1 : 0);

    if (threadIdx.x == 0) {
        #pragma unroll
        for (int s = 0; s < NSTAGES; s++) {
            mbar_init(smem_u32(&full_b[s]), 32);    // 32 producer-thread async arrivals
            mbar_init(smem_u32(&empty_b[s]), 32);   // 32 consumer-thread arrivals
        }
    }
    __syncthreads();

    const float4* const tbox4 = reinterpret_cast<const float4*>(tbox);
    const float4* const pred4 = reinterpret_cast<const float4*>(pred);

    float v = 0.0f;

    if (wid == 7) {
        // ---------------- PRODUCER ----------------
        for (int j = 0; j < cnt; j++) {
            const int s = j % NSTAGES;
            const int k = j / NSTAGES;
            if (k >= 1)
                mbar_wait(smem_u32(&empty_b[s]), (unsigned)((k - 1) & 1));
            issue_tile(sp + s * TWORDS, pred4, start + j, lane);
            cpasync_mbar_arrive_noinc(smem_u32(&full_b[s]));
        }
    } else {
        // ---------------- CONSUMER (warps 0..6) ----------------
        int j = wid;
        float4 tb = {}; int g = 0, tc = 0;
        if (j < cnt) {
            const int c = (start + j) * 32 + lane;
            tb = __ldg(tbox4 + c);
            g  = __ldg(grid + c);
            tc = __ldg(tcls + c);
        }
        while (j < cnt) {
            // prefetch targets for j+7 (overlaps wait + compute)
            const int jn = j + 7;
            float4 tbn = {}; int gn = 0, tcn = 0;
            if (jn < cnt) {
                const int cn = (start + jn) * 32 + lane;
                tbn = __ldg(tbox4 + cn);
                gn  = __ldg(grid + cn);
                tcn = __ldg(tcls + cn);
            }

            const int s = j % NSTAGES;
            const int k = j / NSTAGES;
            mbar_wait(smem_u32(&full_b[s]), (unsigned)(k & 1));

            const float* p = sp + s * TWORDS + lane * 30;
            v += cell_loss(p, (start + j) * 32 + lane, tb, g, tc);
            __syncwarp();
            mbar_arrive(smem_u32(&empty_b[s]));

            j = jn; tb = tbn; g = gn; tc = tcn;
        }
    }

    // ---- block reduction -> g_partials[blockIdx.x] ----
    #pragma unroll
    for (int o = 16; o; o >>= 1) v += __shfl_down_sync(0xffffffffu, v, o);
    if (lane == 0) wsum[wid] = v;
    __syncthreads();
    if (threadIdx.x < NTHREADS / 32) {
        v = wsum[threadIdx.x];
        #pragma unroll
        for (int o = NTHREADS / 64; o; o >>= 1) v += __shfl_down_sync(0xffu, v, o);
        if (threadIdx.x == 0) {
            g_partials[blockIdx.x] = v;
            __threadfence();
            unsigned int prev = atomicInc(&g_done, NBLOCKS - 1);
            s_last = (prev == NBLOCKS - 1);
        }
    }
    __syncthreads();

    // ---- last-arriving block: deterministic final reduction ----
    if (s_last) {
        double acc = 0.0;
        for (int i = threadIdx.x; i < NBLOCKS; i += NTHREADS)
            acc += (double)g_partials[i];
        #pragma unroll
        for (int o = 16; o; o >>= 1) acc += __shfl_down_sync(0xffffffffu, acc, o);
        __shared__ double ws[NTHREADS / 32];
        if (lane == 0) ws[wid] = acc;
        __syncthreads();
        if (threadIdx.x == 0) {
            double sum = 0.0;
            #pragma unroll
            for (int i = 0; i < NTHREADS / 32; i++) sum += ws[i];
            out[0] = (float)(sum / 16384.0);
        }
    }
}

extern "C" void kernel_launch(void* const* d_in, const int* in_sizes, int n_in,
                              void* d_out, int out_size)
{
    const float* pred = (const float*)d_in[0];   // (B, 1470) f32
    const int*   grid = (const int*)  d_in[1];   // (B, 7, 7) i32
    const float* tbox = (const float*)d_in[2];   // (B, 7, 7, 4) f32
    const int*   tcls = (const int*)  d_in[3];   // (B, 7, 7) i32
    float* out = (float*)d_out;

    yolo_loss_kernel<<<NBLOCKS, NTHREADS>>>(pred, grid, tbox, tcls, out);
}